// round 13
// baseline (speedup 1.0000x reference)
#include <cuda_runtime.h>
#include <cuda_bf16.h>
#include <mma.h>
#include <cstdint>
#include <cstddef>

using namespace nvcuda;

#define NN 50000
#define NPAD 50048  // 391 * 128
#define EE 800000
#define EPSBN 1e-5f
#define NTILES 391

// ---------------- scratch (static device globals) ---------------------------
__device__ __align__(256) float g_h[(size_t)NPAD * 256];
__device__ __align__(256) float g_out[(size_t)NN * 256];
__device__ __align__(256) float g_als[NN * 4];
__device__ __align__(256) float g_ald[NN * 4];
__device__ __align__(256) int   g_rowptr[2][NN + 1];
__device__ __align__(256) int   g_colidx[2][EE];
__device__ __align__(256) int   g_deg[2][NN];
__device__ __align__(256) int   g_cursor[2][NN];
__device__ __align__(256) int   g_bsums[2][64];
__device__ __align__(256) float g_bnstat[2][512];
__device__ __align__(256) __nv_bfloat16 g_wt_hi[4 * 256 * 256];  // [layer][n][k]
__device__ __align__(256) __nv_bfloat16 g_wt_lo[4 * 256 * 256];
__device__ __align__(256) __nv_bfloat16 g_a_hi[(size_t)NPAD * 256];
__device__ __align__(256) __nv_bfloat16 g_a_lo[(size_t)NPAD * 256];

__device__ __forceinline__ void split2(float a, float b, uint32_t& hi, uint32_t& lo) {
    __nv_bfloat162 h = __floats2bfloat162_rn(a, b);
    hi = *reinterpret_cast<uint32_t*>(&h);
    float ra = a - __bfloat162float(h.x);
    float rb = b - __bfloat162float(h.y);
    __nv_bfloat162 l = __floats2bfloat162_rn(ra, rb);
    lo = *reinterpret_cast<uint32_t*>(&l);
}

__device__ __forceinline__ uint32_t smem_u32(const void* p) {
    uint32_t a;
    asm("{ .reg .u64 t; cvta.to.shared.u64 t, %1; cvt.u32.u64 %0, t; }" : "=r"(a) : "l"(p));
    return a;
}
__device__ __forceinline__ void cp16(uint32_t s, const void* g) {
    asm volatile("cp.async.cg.shared.global [%0], [%1], 16;" :: "r"(s), "l"(g));
}
#define CP_COMMIT asm volatile("cp.async.commit_group;")

// ---------------- W preprocessing -------------------------------------------
__global__ void k_wprep(const float* __restrict__ W1, const float* __restrict__ W2,
                        const float* __restrict__ W3, const float* __restrict__ W4) {
    int layer = blockIdx.y;
    const float* W = layer == 0 ? W1 : layer == 1 ? W2 : layer == 2 ? W3 : W4;
    int K = layer == 0 ? 128 : 256;
    int i = blockIdx.x * 256 + threadIdx.x;  // i = n*256 + k
    int n = i >> 8, k = i & 255;
    float v = (k < K) ? W[k * 256 + n] : 0.0f;
    __nv_bfloat16 h = __float2bfloat16_rn(v);
    float lo = v - __bfloat162float(h);
    g_wt_hi[layer * 65536 + i] = h;
    g_wt_lo[layer * 65536 + i] = __float2bfloat16_rn(lo);
}

// ---------------- x preprocessing -------------------------------------------
__global__ void k_xprep(const float* __restrict__ x) {
    int i = blockIdx.x * 256 + threadIdx.x;  // over NN*32 float4s
    if (i >= NN * 32) return;
    float4 v = ((const float4*)x)[i];
    uint32_t h01, l01, h23, l23;
    split2(v.x, v.y, h01, l01);
    split2(v.z, v.w, h23, l23);
    *(uint2*)(g_a_hi + (size_t)i * 4) = make_uint2(h01, h23);
    *(uint2*)(g_a_lo + (size_t)i * 4) = make_uint2(l01, l23);
}

// ---------------- WMMA bf16 split GEMM, 2 CTAs/SM (round-11 proven) ----------
typedef wmma::fragment<wmma::matrix_a, 16, 16, 16, __nv_bfloat16, wmma::row_major> FragA;
typedef wmma::fragment<wmma::matrix_b, 16, 16, 16, __nv_bfloat16, wmma::col_major> FragB;
typedef wmma::fragment<wmma::accumulator, 16, 16, 16, float> FragC;

#define SSTR 40
#define PSTG 5120
#define SMEM_GEMM 81920

__global__ __launch_bounds__(256, 2) void k_gemm2(int K, int layer) {
    extern __shared__ __nv_bfloat16 sm[];
    const __nv_bfloat16* gAh = g_a_hi;
    const __nv_bfloat16* gAl = g_a_lo;
    const __nv_bfloat16* gBh = g_wt_hi + layer * 65536;
    const __nv_bfloat16* gBl = g_wt_lo + layer * 65536;
    int tid = threadIdx.x, wid = tid >> 5;
    int tbM = blockIdx.x * 128, tbN = blockIdx.y * 128;
    int wm = wid & 1, wn = wid >> 1;
    uint32_t sbase = smem_u32(sm);

    FragC acc[4][2];
#pragma unroll
    for (int i = 0; i < 4; i++)
#pragma unroll
        for (int j = 0; j < 2; j++) wmma::fill_fragment(acc[i][j], 0.0f);

    int nch = K >> 5;

#define PREFETCH(stage, k0)                                                        \
    {                                                                              \
        _Pragma("unroll")                                                          \
        for (int r = 0; r < 2; r++) {                                              \
            int q = r * 256 + tid;                                                 \
            int row = q >> 2;                                                      \
            int cq = (q & 3) * 8;                                                  \
            size_t ga = (size_t)(tbM + row) * K + (k0) + cq;                       \
            size_t gb = (size_t)(tbN + row) * 256 + (k0) + cq;                     \
            uint32_t so = (uint32_t)(((stage) * 2) * PSTG + row * SSTR + cq) * 2;  \
            cp16(sbase + so, gAh + ga);                                            \
            cp16(sbase + so + PSTG * 2, gAl + ga);                                 \
            cp16(sbase + so + 4 * PSTG * 2, gBh + gb);                             \
            cp16(sbase + so + 5 * PSTG * 2, gBl + gb);                             \
        }                                                                          \
    }

    PREFETCH(0, 0);
    CP_COMMIT;
    for (int c = 0; c < nch; c++) {
        if (c + 1 < nch) {
            PREFETCH((c + 1) & 1, (c + 1) * 32);
            CP_COMMIT;
            asm volatile("cp.async.wait_group 1;");
        } else {
            asm volatile("cp.async.wait_group 0;");
        }
        __syncthreads();
        int st = c & 1;
        const __nv_bfloat16* pAh = sm + (st * 2 + 0) * PSTG;
        const __nv_bfloat16* pAl = sm + (st * 2 + 1) * PSTG;
        const __nv_bfloat16* pBh = sm + 4 * PSTG + (st * 2 + 0) * PSTG;
        const __nv_bfloat16* pBl = sm + 4 * PSTG + (st * 2 + 1) * PSTG;
#pragma unroll
        for (int ks = 0; ks < 32; ks += 16) {
            FragB bhi[2], blo[2];
#pragma unroll
            for (int j = 0; j < 2; j++) {
                wmma::load_matrix_sync(bhi[j], &pBh[(wn * 32 + j * 16) * SSTR + ks], SSTR);
                wmma::load_matrix_sync(blo[j], &pBl[(wn * 32 + j * 16) * SSTR + ks], SSTR);
            }
#pragma unroll
            for (int i = 0; i < 4; i++) {
                FragA ah, al;
                wmma::load_matrix_sync(ah, &pAh[(wm * 64 + i * 16) * SSTR + ks], SSTR);
                wmma::load_matrix_sync(al, &pAl[(wm * 64 + i * 16) * SSTR + ks], SSTR);
#pragma unroll
                for (int j = 0; j < 2; j++) {
                    wmma::mma_sync(acc[i][j], ah, bhi[j], acc[i][j]);
                    wmma::mma_sync(acc[i][j], ah, blo[j], acc[i][j]);
                    wmma::mma_sync(acc[i][j], al, bhi[j], acc[i][j]);
                }
            }
        }
        __syncthreads();
    }

#pragma unroll
    for (int i = 0; i < 4; i++)
#pragma unroll
        for (int j = 0; j < 2; j++)
            wmma::store_matrix_sync(
                g_h + (size_t)(tbM + wm * 64 + i * 16) * 256 + tbN + wn * 32 + j * 16,
                acc[i][j], 256, wmma::mem_row_major);
}

// ---------------- attention logits per node ---------------------------------
__global__ void k_al(const float* __restrict__ as_, const float* __restrict__ ad_) {
    int gt = blockIdx.x * blockDim.x + threadIdx.x;
    int w = gt >> 5, lane = gt & 31;
    if (w >= NN) return;
    const float4* hp = (const float4*)(g_h + (size_t)w * 256);
    float4 h1 = hp[lane * 2], h2 = hp[lane * 2 + 1];
    const float4* sp = (const float4*)as_;
    const float4* dp = (const float4*)ad_;
    float4 s1 = sp[lane * 2], s2 = sp[lane * 2 + 1];
    float4 d1 = dp[lane * 2], d2 = dp[lane * 2 + 1];
    float vs = h1.x * s1.x + h1.y * s1.y + h1.z * s1.z + h1.w * s1.w +
               h2.x * s2.x + h2.y * s2.y + h2.z * s2.z + h2.w * s2.w;
    float vd = h1.x * d1.x + h1.y * d1.y + h1.z * d1.z + h1.w * d1.w +
               h2.x * d2.x + h2.y * d2.y + h2.z * d2.z + h2.w * d2.w;
    vs += __shfl_down_sync(0xffffffffu, vs, 4, 8);
    vs += __shfl_down_sync(0xffffffffu, vs, 2, 8);
    vs += __shfl_down_sync(0xffffffffu, vs, 1, 8);
    vd += __shfl_down_sync(0xffffffffu, vd, 4, 8);
    vd += __shfl_down_sync(0xffffffffu, vd, 2, 8);
    vd += __shfl_down_sync(0xffffffffu, vd, 1, 8);
    if ((lane & 7) == 0) {
        g_als[w * 4 + (lane >> 3)] = vs;
        g_ald[w * 4 + (lane >> 3)] = vd;
    }
}

// ---------------- small utility kernels --------------------------------------
__global__ void k_zero_deg() {
    int i = blockIdx.x * blockDim.x + threadIdx.x;
    if (i < 2 * NN) ((int*)g_deg)[i] = 0;
}
__global__ void k_zero_bn() {
    int i = threadIdx.x;
    g_bnstat[0][i] = 0.0f;
    g_bnstat[1][i] = 0.0f;
}

// ---------------- CSR build (batched over both edge types) -------------------
__global__ void k_hist2(const int* __restrict__ eis, const int* __restrict__ eit) {
    int e = blockIdx.x * blockDim.x + threadIdx.x;
    if (e < EE) {
        atomicAdd(&g_deg[0][eis[EE + e]], 1);
        atomicAdd(&g_deg[1][eit[EE + e]], 1);
    }
}
__global__ void k_scan1() {
    int et = blockIdx.y;
    __shared__ int sm[1024];
    int t = threadIdx.x;
    int idx = blockIdx.x * 1024 + t;
    int v = (idx < NN) ? g_deg[et][idx] : 0;
    sm[t] = v;
    __syncthreads();
    for (int off = 1; off < 1024; off <<= 1) {
        int u = (t >= off) ? sm[t - off] : 0;
        __syncthreads();
        sm[t] += u;
        __syncthreads();
    }
    if (idx < NN) g_rowptr[et][idx + 1] = sm[t];
    if (t == 1023) g_bsums[et][blockIdx.x] = sm[1023];
}
__global__ void k_scan2(int nb) {
    int et = blockIdx.x;
    int t = threadIdx.x, lane = t & 31, wd = t >> 5;
    int v = (t < nb) ? g_bsums[et][t] : 0;
    int orig = v;
#pragma unroll
    for (int off = 1; off < 32; off <<= 1) {
        int u = __shfl_up_sync(0xffffffffu, v, off);
        if (lane >= off) v += u;
    }
    __shared__ int wtot;
    if (wd == 0 && lane == 31) wtot = v;
    __syncthreads();
    if (wd == 1) v += wtot;
    if (t < nb) g_bsums[et][t] = v - orig;
}
__global__ void k_scan3() {
    int et = blockIdx.y;
    int idx = blockIdx.x * 1024 + threadIdx.x;
    if (idx < NN) {
        int v = g_rowptr[et][idx + 1] + g_bsums[et][blockIdx.x];
        g_rowptr[et][idx + 1] = v;
        if (idx + 1 < NN) g_cursor[et][idx + 1] = v;
    }
    if (idx == 0) { g_rowptr[et][0] = 0; g_cursor[et][0] = 0; }
}
__global__ void k_scatter2(const int* __restrict__ eis, const int* __restrict__ eit) {
    int et = blockIdx.y;
    const int* ei = et ? eit : eis;
    int e = blockIdx.x * blockDim.x + threadIdx.x;
    if (e < EE) {
        int dst = ei[EE + e];
        int pos = atomicAdd(&g_cursor[et][dst], 1);
        g_colidx[et][pos] = ei[e];
    }
}

// ---------------- aggregation + fused BN stats -------------------------------
__device__ __forceinline__ float lrelu02(float x) { return x > 0.f ? x : 0.2f * x; }

__global__ __launch_bounds__(256) void k_agg(int et, const float* __restrict__ bias, int buf) {
    __shared__ float ssum[8 * 512];
    __shared__ float ssq[8 * 512];
    int gt = blockIdx.x * blockDim.x + threadIdx.x;
    int w = gt >> 5, lane = gt & 31;
    int tid = threadIdx.x, wid = tid >> 5;

    const float4 ald = *(const float4*)(g_ald + (size_t)w * 4);
    int start = g_rowptr[et][w];
    int end = g_rowptr[et][w + 1];
    int hsel = lane >> 4;

    float4 acc1 = make_float4(0, 0, 0, 0);
    float4 acc2 = make_float4(0, 0, 0, 0);
    float se0 = 0, se1 = 0, se2 = 0, se3 = 0;

#define EDGE(SRC, X0, X1, X2, X3)                                              \
    {                                                                          \
        float ex1 = hsel ? (X1) : (X0);                                        \
        float ex2 = hsel ? (X3) : (X2);                                        \
        const float4* hp = (const float4*)(g_h + (size_t)(SRC) * 256);         \
        float4 v1 = hp[lane], v2 = hp[32 + lane];                              \
        acc1.x += ex1 * v1.x; acc1.y += ex1 * v1.y;                            \
        acc1.z += ex1 * v1.z; acc1.w += ex1 * v1.w;                            \
        acc2.x += ex2 * v2.x; acc2.y += ex2 * v2.y;                            \
        acc2.z += ex2 * v2.z; acc2.w += ex2 * v2.w;                            \
    }

    // self loop
    {
        float4 als = *(const float4*)(g_als + (size_t)w * 4);
        float x0 = __expf(lrelu02(als.x + ald.x));
        float x1 = __expf(lrelu02(als.y + ald.y));
        float x2 = __expf(lrelu02(als.z + ald.z));
        float x3 = __expf(lrelu02(als.w + ald.w));
        if (lane == 0) { se0 += x0; se1 += x1; se2 += x2; se3 += x3; }
        EDGE(w, x0, x1, x2, x3);
    }

    for (int base = start; base < end; base += 32) {
        int n = min(32, end - base);
        int mysrc = 0;
        float mx0 = 0.f, mx1 = 0.f, mx2 = 0.f, mx3 = 0.f;
        if (base + lane < end) {
            mysrc = g_colidx[et][base + lane];
            float4 als = *(const float4*)(g_als + (size_t)mysrc * 4);
            mx0 = __expf(lrelu02(als.x + ald.x));
            mx1 = __expf(lrelu02(als.y + ald.y));
            mx2 = __expf(lrelu02(als.z + ald.z));
            mx3 = __expf(lrelu02(als.w + ald.w));
            se0 += mx0; se1 += mx1; se2 += mx2; se3 += mx3;
        }
        int j = 0;
        for (; j + 4 <= n; j += 4) {
            int src0 = __shfl_sync(0xffffffffu, mysrc, j);
            int src1 = __shfl_sync(0xffffffffu, mysrc, j + 1);
            int src2 = __shfl_sync(0xffffffffu, mysrc, j + 2);
            int src3 = __shfl_sync(0xffffffffu, mysrc, j + 3);
            float e0, e1, e2, e3;
            {
                float a0 = __shfl_sync(0xffffffffu, mx0, j);
                float a1 = __shfl_sync(0xffffffffu, mx1, j);
                float a2 = __shfl_sync(0xffffffffu, mx2, j);
                float a3 = __shfl_sync(0xffffffffu, mx3, j);
                e0 = hsel ? a1 : a0;
                e1 = hsel ? a3 : a2;
                float b0 = __shfl_sync(0xffffffffu, mx0, j + 1);
                float b1 = __shfl_sync(0xffffffffu, mx1, j + 1);
                float b2 = __shfl_sync(0xffffffffu, mx2, j + 1);
                float b3 = __shfl_sync(0xffffffffu, mx3, j + 1);
                e2 = hsel ? b1 : b0;
                e3 = hsel ? b3 : b2;
            }
            float f0, f1, f2, f3;
            {
                float a0 = __shfl_sync(0xffffffffu, mx0, j + 2);
                float a1 = __shfl_sync(0xffffffffu, mx1, j + 2);
                float a2 = __shfl_sync(0xffffffffu, mx2, j + 2);
                float a3 = __shfl_sync(0xffffffffu, mx3, j + 2);
                f0 = hsel ? a1 : a0;
                f1 = hsel ? a3 : a2;
                float b0 = __shfl_sync(0xffffffffu, mx0, j + 3);
                float b1 = __shfl_sync(0xffffffffu, mx1, j + 3);
                float b2 = __shfl_sync(0xffffffffu, mx2, j + 3);
                float b3 = __shfl_sync(0xffffffffu, mx3, j + 3);
                f2 = hsel ? b1 : b0;
                f3 = hsel ? b3 : b2;
            }
            const float4* hp0 = (const float4*)(g_h + (size_t)src0 * 256);
            const float4* hp1 = (const float4*)(g_h + (size_t)src1 * 256);
            const float4* hp2 = (const float4*)(g_h + (size_t)src2 * 256);
            const float4* hp3 = (const float4*)(g_h + (size_t)src3 * 256);
            float4 vA1 = hp0[lane], vA2 = hp0[32 + lane];
            float4 vB1 = hp1[lane], vB2 = hp1[32 + lane];
            float4 vC1 = hp2[lane], vC2 = hp2[32 + lane];
            float4 vD1 = hp3[lane], vD2 = hp3[32 + lane];
            acc1.x += e0 * vA1.x + e2 * vB1.x + f0 * vC1.x + f2 * vD1.x;
            acc1.y += e0 * vA1.y + e2 * vB1.y + f0 * vC1.y + f2 * vD1.y;
            acc1.z += e0 * vA1.z + e2 * vB1.z + f0 * vC1.z + f2 * vD1.z;
            acc1.w += e0 * vA1.w + e2 * vB1.w + f0 * vC1.w + f2 * vD1.w;
            acc2.x += e1 * vA2.x + e3 * vB2.x + f1 * vC2.x + f3 * vD2.x;
            acc2.y += e1 * vA2.y + e3 * vB2.y + f1 * vC2.y + f3 * vD2.y;
            acc2.z += e1 * vA2.z + e3 * vB2.z + f1 * vC2.z + f3 * vD2.z;
            acc2.w += e1 * vA2.w + e3 * vB2.w + f1 * vC2.w + f3 * vD2.w;
        }
        for (; j < n; j++) {
            int src = __shfl_sync(0xffffffffu, mysrc, j);
            float x0 = __shfl_sync(0xffffffffu, mx0, j);
            float x1 = __shfl_sync(0xffffffffu, mx1, j);
            float x2 = __shfl_sync(0xffffffffu, mx2, j);
            float x3 = __shfl_sync(0xffffffffu, mx3, j);
            EDGE(src, x0, x1, x2, x3);
        }
    }
#undef EDGE

#pragma unroll
    for (int off = 16; off; off >>= 1) {
        se0 += __shfl_xor_sync(0xffffffffu, se0, off);
        se1 += __shfl_xor_sync(0xffffffffu, se1, off);
        se2 += __shfl_xor_sync(0xffffffffu, se2, off);
        se3 += __shfl_xor_sync(0xffffffffu, se3, off);
    }

    float inv1 = 1.0f / ((hsel ? se1 : se0) + 1e-16f);
    float inv2 = 1.0f / ((hsel ? se3 : se2) + 1e-16f);
    const float4* bp = (const float4*)bias;
    float4 b1 = bp[lane], b2 = bp[32 + lane];
    float4 o1 = make_float4(acc1.x * inv1 + b1.x, acc1.y * inv1 + b1.y,
                            acc1.z * inv1 + b1.z, acc1.w * inv1 + b1.w);
    float4 o2 = make_float4(acc2.x * inv2 + b2.x, acc2.y * inv2 + b2.y,
                            acc2.z * inv2 + b2.z, acc2.w * inv2 + b2.w);
    *(float4*)(g_out + (size_t)w * 256 + lane * 4) = o1;
    *(float4*)(g_out + (size_t)w * 256 + 128 + lane * 4) = o2;

    // ---- fused BN statistics ----
    ((float4*)ssum)[wid * 128 + lane] = o1;
    ((float4*)ssum)[wid * 128 + 32 + lane] = o2;
    float4 q1 = make_float4(o1.x * o1.x, o1.y * o1.y, o1.z * o1.z, o1.w * o1.w);
    float4 q2 = make_float4(o2.x * o2.x, o2.y * o2.y, o2.z * o2.z, o2.w * o2.w);
    ((float4*)ssq)[wid * 128 + lane] = q1;
    ((float4*)ssq)[wid * 128 + 32 + lane] = q2;
    __syncthreads();
    {
        int col = tid;
        float s = 0.f, q = 0.f;
#pragma unroll
        for (int wd = 0; wd < 8; wd++) {
            s += ssum[wd * 512 + col];
            q += ssq[wd * 512 + col];
        }
        atomicAdd(&g_bnstat[buf][col], s);
        atomicAdd(&g_bnstat[buf][256 + col], q);
    }
}

// ---------------- BN apply + ReLU + bf16 hi/lo split -------------------------
__global__ void k_bnsplit(int buf, const float* __restrict__ gam,
                          const float* __restrict__ bet) {
    int i = blockIdx.x * blockDim.x + threadIdx.x;
    if (i < 512) g_bnstat[buf ^ 1][i] = 0.0f;
    if (i >= NN * 64) return;
    int colb = (i & 63) * 4;
    float4 v = ((const float4*)g_out)[i];
    float invN = 1.0f / (float)NN;
    float out[4];
    float vv[4] = {v.x, v.y, v.z, v.w};
#pragma unroll
    for (int c = 0; c < 4; c++) {
        float mu = g_bnstat[buf][colb + c] * invN;
        float var = g_bnstat[buf][256 + colb + c] * invN - mu * mu;
        float sc = gam[colb + c] * rsqrtf(var + EPSBN);
        float y = (vv[c] - mu) * sc + bet[colb + c];
        out[c] = y > 0.f ? y : 0.f;
    }
    uint32_t h01, l01, h23, l23;
    split2(out[0], out[1], h01, l01);
    split2(out[2], out[3], h23, l23);
    *(uint2*)(g_a_hi + (size_t)i * 4) = make_uint2(h01, h23);
    *(uint2*)(g_a_lo + (size_t)i * 4) = make_uint2(l01, l23);
}

// ---------------- final linear 256 -> 32 --------------------------------------
__global__ void k_lin(const float* __restrict__ Wl, const float* __restrict__ bl,
                      float* __restrict__ out) {
    int gt = blockIdx.x * blockDim.x + threadIdx.x;
    int w = gt >> 5, lane = gt & 31;
    if (w >= NN) return;
    float acc = bl[lane];
    const __nv_bfloat16* ah = g_a_hi + (size_t)w * 256;
    const __nv_bfloat16* al = g_a_lo + (size_t)w * 256;
    for (int kb = 0; kb < 256; kb += 32) {
        float av = __bfloat162float(ah[kb + lane]) + __bfloat162float(al[kb + lane]);
#pragma unroll
        for (int kk = 0; kk < 32; kk++) {
            float a = __shfl_sync(0xffffffffu, av, kk);
            acc += a * Wl[(kb + kk) * 32 + lane];
        }
    }
    out[(size_t)w * 32 + lane] = acc;
}

// ---------------- launch ------------------------------------------------------
extern "C" void kernel_launch(void* const* d_in, const int* in_sizes, int n_in,
                              void* d_out, int out_size) {
    (void)in_sizes; (void)n_in; (void)out_size;
    const float* x = (const float*)d_in[0];
    const int* eis = (const int*)d_in[1];
    const int* eit = (const int*)d_in[2];
    const float* W[4]  = {(const float*)d_in[3],  (const float*)d_in[9],
                          (const float*)d_in[15], (const float*)d_in[21]};
    const float* AS[4] = {(const float*)d_in[4],  (const float*)d_in[10],
                          (const float*)d_in[16], (const float*)d_in[22]};
    const float* AD[4] = {(const float*)d_in[5],  (const float*)d_in[11],
                          (const float*)d_in[17], (const float*)d_in[23]};
    const float* BI[4] = {(const float*)d_in[6],  (const float*)d_in[12],
                          (const float*)d_in[18], (const float*)d_in[24]};
    const float* GA[4] = {(const float*)d_in[7],  (const float*)d_in[13],
                          (const float*)d_in[19], (const float*)d_in[25]};
    const float* BE[4] = {(const float*)d_in[8],  (const float*)d_in[14],
                          (const float*)d_in[20], (const float*)d_in[26]};
    const float* Wl = (const float*)d_in[27];
    const float* bl = (const float*)d_in[28];

    static cudaStream_t s1 = nullptr;
    static cudaEvent_t evFork = nullptr, evJoin = nullptr;
    if (s1 == nullptr) {
        cudaStreamCreateWithFlags(&s1, cudaStreamNonBlocking);
        cudaEventCreateWithFlags(&evFork, cudaEventDisableTiming);
        cudaEventCreateWithFlags(&evJoin, cudaEventDisableTiming);
        cudaFuncSetAttribute(k_gemm2, cudaFuncAttributeMaxDynamicSharedMemorySize,
                             SMEM_GEMM);
    }

    const int scanBlocks = (NN + 1023) / 1024;  // 49
    dim3 ggemm(NTILES, 2);

    // main stream: prep + layer-0 GEMM
    k_wprep<<<dim3(256, 4), 256>>>(W[0], W[1], W[2], W[3]);
    k_xprep<<<(NN * 32 + 255) / 256, 256>>>(x);
    k_zero_bn<<<1, 512>>>();
    cudaEventRecord(evFork, 0);
    k_gemm2<<<ggemm, 256, SMEM_GEMM>>>(128, 0);

    // forked stream: full CSR build for both edge types
    cudaStreamWaitEvent(s1, evFork, 0);
    k_zero_deg<<<(2 * NN + 255) / 256, 256, 0, s1>>>();
    k_hist2<<<(EE + 255) / 256, 256, 0, s1>>>(eis, eit);
    k_scan1<<<dim3(scanBlocks, 2), 1024, 0, s1>>>();
    k_scan2<<<2, 64, 0, s1>>>(scanBlocks);
    k_scan3<<<dim3(scanBlocks, 2), 1024, 0, s1>>>();
    k_scatter2<<<dim3((EE + 255) / 256, 2), 256, 0, s1>>>(eis, eit);
    cudaEventRecord(evJoin, s1);

    k_al<<<(NN * 32 + 255) / 256, 256>>>(AS[0], AD[0]);
    cudaStreamWaitEvent(0, evJoin, 0);

    int ET[4] = {0, 0, 1, 1};
    for (int l = 0; l < 4; l++) {
        if (l > 0) {
            k_gemm2<<<ggemm, 256, SMEM_GEMM>>>(256, l);
            k_al<<<(NN * 32 + 255) / 256, 256>>>(AS[l], AD[l]);
        }
        k_agg<<<(NN * 32 + 255) / 256, 256>>>(ET[l], BI[l], l & 1);
        k_bnsplit<<<(NN * 64 + 255) / 256, 256>>>(l & 1, GA[l], BE[l]);
    }
    k_lin<<<(NN * 32 + 255) / 256, 256>>>(Wl, bl, (float*)d_out);
}

// round 15
// speedup vs baseline: 1.0217x; 1.0217x over previous
#include <cuda_runtime.h>
#include <cuda_bf16.h>
#include <mma.h>
#include <cstdint>
#include <cstddef>

using namespace nvcuda;

#define NN 50000
#define NPAD 50048  // 391 * 128
#define EE 800000
#define EPSBN 1e-5f
#define NTILES 391

// ---------------- scratch (static device globals) ---------------------------
__device__ __align__(256) float g_h[(size_t)NPAD * 256];
__device__ __align__(256) float g_out[(size_t)NN * 256];
__device__ __align__(256) float g_als[NN * 4];
__device__ __align__(256) float g_ald[NN * 4];
__device__ __align__(256) int   g_rowptr[2][NN + 1];
__device__ __align__(256) int   g_colidx[2][EE];
__device__ __align__(256) int   g_deg[2][NN];
__device__ __align__(256) int   g_cursor[2][NN];
__device__ __align__(256) int   g_bsums[2][64];
__device__ __align__(256) float g_bnstat[2][512];
__device__ __align__(256) __nv_bfloat16 g_wt_hi[4 * 256 * 256];  // [layer][n][k]
__device__ __align__(256) __nv_bfloat16 g_wt_lo[4 * 256 * 256];
__device__ __align__(256) __nv_bfloat16 g_a_hi[(size_t)NPAD * 256];
__device__ __align__(256) __nv_bfloat16 g_a_lo[(size_t)NPAD * 256];

__device__ __forceinline__ void split2(float a, float b, uint32_t& hi, uint32_t& lo) {
    __nv_bfloat162 h = __floats2bfloat162_rn(a, b);
    hi = *reinterpret_cast<uint32_t*>(&h);
    float ra = a - __bfloat162float(h.x);
    float rb = b - __bfloat162float(h.y);
    __nv_bfloat162 l = __floats2bfloat162_rn(ra, rb);
    lo = *reinterpret_cast<uint32_t*>(&l);
}

__device__ __forceinline__ uint32_t smem_u32(const void* p) {
    uint32_t a;
    asm("{ .reg .u64 t; cvta.to.shared.u64 t, %1; cvt.u32.u64 %0, t; }" : "=r"(a) : "l"(p));
    return a;
}
__device__ __forceinline__ void cp16(uint32_t s, const void* g) {
    asm volatile("cp.async.cg.shared.global [%0], [%1], 16;" :: "r"(s), "l"(g));
}
#define CP_COMMIT asm volatile("cp.async.commit_group;")

// ---------------- fused prep: W split + x split + bn zero --------------------
// blocks [0,1024): W prep (4 layers x 256 blocks); blocks 0,1 also zero g_bnstat
// blocks [1024, 1024+6250): x prep
__global__ void k_prep(const float* __restrict__ x,
                       const float* __restrict__ W1, const float* __restrict__ W2,
                       const float* __restrict__ W3, const float* __restrict__ W4) {
    int b = blockIdx.x;
    int tid = threadIdx.x;
    if (b < 2) {
        g_bnstat[b][tid] = 0.0f;
        g_bnstat[b][tid + 256] = 0.0f;
    }
    if (b < 1024) {
        int layer = b >> 8;
        const float* W = layer == 0 ? W1 : layer == 1 ? W2 : layer == 2 ? W3 : W4;
        int K = layer == 0 ? 128 : 256;
        int i = (b & 255) * 256 + tid;  // i = n*256 + k
        int n = i >> 8, k = i & 255;
        float v = (k < K) ? W[k * 256 + n] : 0.0f;
        __nv_bfloat16 h = __float2bfloat16_rn(v);
        float lo = v - __bfloat162float(h);
        g_wt_hi[layer * 65536 + i] = h;
        g_wt_lo[layer * 65536 + i] = __float2bfloat16_rn(lo);
    } else {
        int i = (b - 1024) * 256 + tid;  // over NN*32 float4s
        if (i >= NN * 32) return;
        float4 v = ((const float4*)x)[i];
        uint32_t h01, l01, h23, l23;
        split2(v.x, v.y, h01, l01);
        split2(v.z, v.w, h23, l23);
        *(uint2*)(g_a_hi + (size_t)i * 4) = make_uint2(h01, h23);
        *(uint2*)(g_a_lo + (size_t)i * 4) = make_uint2(l01, l23);
    }
}

// ---------------- WMMA bf16 split GEMM, 2 CTAs/SM (round-11 proven) ----------
typedef wmma::fragment<wmma::matrix_a, 16, 16, 16, __nv_bfloat16, wmma::row_major> FragA;
typedef wmma::fragment<wmma::matrix_b, 16, 16, 16, __nv_bfloat16, wmma::col_major> FragB;
typedef wmma::fragment<wmma::accumulator, 16, 16, 16, float> FragC;

#define SSTR 40
#define PSTG 5120
#define SMEM_GEMM 81920

__global__ __launch_bounds__(256, 2) void k_gemm2(int K, int layer) {
    extern __shared__ __nv_bfloat16 sm[];
    const __nv_bfloat16* gAh = g_a_hi;
    const __nv_bfloat16* gAl = g_a_lo;
    const __nv_bfloat16* gBh = g_wt_hi + layer * 65536;
    const __nv_bfloat16* gBl = g_wt_lo + layer * 65536;
    int tid = threadIdx.x, wid = tid >> 5;
    int tbM = blockIdx.x * 128, tbN = blockIdx.y * 128;
    int wm = wid & 1, wn = wid >> 1;
    uint32_t sbase = smem_u32(sm);

    FragC acc[4][2];
#pragma unroll
    for (int i = 0; i < 4; i++)
#pragma unroll
        for (int j = 0; j < 2; j++) wmma::fill_fragment(acc[i][j], 0.0f);

    int nch = K >> 5;

#define PREFETCH(stage, k0)                                                        \
    {                                                                              \
        _Pragma("unroll")                                                          \
        for (int r = 0; r < 2; r++) {                                              \
            int q = r * 256 + tid;                                                 \
            int row = q >> 2;                                                      \
            int cq = (q & 3) * 8;                                                  \
            size_t ga = (size_t)(tbM + row) * K + (k0) + cq;                       \
            size_t gb = (size_t)(tbN + row) * 256 + (k0) + cq;                     \
            uint32_t so = (uint32_t)(((stage) * 2) * PSTG + row * SSTR + cq) * 2;  \
            cp16(sbase + so, gAh + ga);                                            \
            cp16(sbase + so + PSTG * 2, gAl + ga);                                 \
            cp16(sbase + so + 4 * PSTG * 2, gBh + gb);                             \
            cp16(sbase + so + 5 * PSTG * 2, gBl + gb);                             \
        }                                                                          \
    }

    PREFETCH(0, 0);
    CP_COMMIT;
    for (int c = 0; c < nch; c++) {
        if (c + 1 < nch) {
            PREFETCH((c + 1) & 1, (c + 1) * 32);
            CP_COMMIT;
            asm volatile("cp.async.wait_group 1;");
        } else {
            asm volatile("cp.async.wait_group 0;");
        }
        __syncthreads();
        int st = c & 1;
        const __nv_bfloat16* pAh = sm + (st * 2 + 0) * PSTG;
        const __nv_bfloat16* pAl = sm + (st * 2 + 1) * PSTG;
        const __nv_bfloat16* pBh = sm + 4 * PSTG + (st * 2 + 0) * PSTG;
        const __nv_bfloat16* pBl = sm + 4 * PSTG + (st * 2 + 1) * PSTG;
#pragma unroll
        for (int ks = 0; ks < 32; ks += 16) {
            FragB bhi[2], blo[2];
#pragma unroll
            for (int j = 0; j < 2; j++) {
                wmma::load_matrix_sync(bhi[j], &pBh[(wn * 32 + j * 16) * SSTR + ks], SSTR);
                wmma::load_matrix_sync(blo[j], &pBl[(wn * 32 + j * 16) * SSTR + ks], SSTR);
            }
#pragma unroll
            for (int i = 0; i < 4; i++) {
                FragA ah, al;
                wmma::load_matrix_sync(ah, &pAh[(wm * 64 + i * 16) * SSTR + ks], SSTR);
                wmma::load_matrix_sync(al, &pAl[(wm * 64 + i * 16) * SSTR + ks], SSTR);
#pragma unroll
                for (int j = 0; j < 2; j++) {
                    wmma::mma_sync(acc[i][j], ah, bhi[j], acc[i][j]);
                    wmma::mma_sync(acc[i][j], ah, blo[j], acc[i][j]);
                    wmma::mma_sync(acc[i][j], al, bhi[j], acc[i][j]);
                }
            }
        }
        __syncthreads();
    }

#pragma unroll
    for (int i = 0; i < 4; i++)
#pragma unroll
        for (int j = 0; j < 2; j++)
            wmma::store_matrix_sync(
                g_h + (size_t)(tbM + wm * 64 + i * 16) * 256 + tbN + wn * 32 + j * 16,
                acc[i][j], 256, wmma::mem_row_major);
}

// ---------------- attention logits per node ---------------------------------
__global__ void k_al(const float* __restrict__ as_, const float* __restrict__ ad_) {
    int gt = blockIdx.x * blockDim.x + threadIdx.x;
    int w = gt >> 5, lane = gt & 31;
    if (w >= NN) return;
    const float4* hp = (const float4*)(g_h + (size_t)w * 256);
    float4 h1 = hp[lane * 2], h2 = hp[lane * 2 + 1];
    const float4* sp = (const float4*)as_;
    const float4* dp = (const float4*)ad_;
    float4 s1 = sp[lane * 2], s2 = sp[lane * 2 + 1];
    float4 d1 = dp[lane * 2], d2 = dp[lane * 2 + 1];
    float vs = h1.x * s1.x + h1.y * s1.y + h1.z * s1.z + h1.w * s1.w +
               h2.x * s2.x + h2.y * s2.y + h2.z * s2.z + h2.w * s2.w;
    float vd = h1.x * d1.x + h1.y * d1.y + h1.z * d1.z + h1.w * d1.w +
               h2.x * d2.x + h2.y * d2.y + h2.z * d2.z + h2.w * d2.w;
    vs += __shfl_down_sync(0xffffffffu, vs, 4, 8);
    vs += __shfl_down_sync(0xffffffffu, vs, 2, 8);
    vs += __shfl_down_sync(0xffffffffu, vs, 1, 8);
    vd += __shfl_down_sync(0xffffffffu, vd, 4, 8);
    vd += __shfl_down_sync(0xffffffffu, vd, 2, 8);
    vd += __shfl_down_sync(0xffffffffu, vd, 1, 8);
    if ((lane & 7) == 0) {
        g_als[w * 4 + (lane >> 3)] = vs;
        g_ald[w * 4 + (lane >> 3)] = vd;
    }
}

// ---------------- small utility kernels --------------------------------------
__global__ void k_zero_deg() {
    int i = blockIdx.x * blockDim.x + threadIdx.x;
    if (i < 2 * NN) ((int*)g_deg)[i] = 0;
}

// ---------------- CSR build (batched over both edge types) -------------------
__global__ void k_hist2(const int* __restrict__ eis, const int* __restrict__ eit) {
    int e = blockIdx.x * blockDim.x + threadIdx.x;
    if (e < EE) {
        atomicAdd(&g_deg[0][eis[EE + e]], 1);
        atomicAdd(&g_deg[1][eit[EE + e]], 1);
    }
}
__global__ void k_scan1() {
    int et = blockIdx.y;
    __shared__ int sm[1024];
    int t = threadIdx.x;
    int idx = blockIdx.x * 1024 + t;
    int v = (idx < NN) ? g_deg[et][idx] : 0;
    sm[t] = v;
    __syncthreads();
    for (int off = 1; off < 1024; off <<= 1) {
        int u = (t >= off) ? sm[t - off] : 0;
        __syncthreads();
        sm[t] += u;
        __syncthreads();
    }
    if (idx < NN) g_rowptr[et][idx + 1] = sm[t];
    if (t == 1023) g_bsums[et][blockIdx.x] = sm[1023];
}
__global__ void k_scan2(int nb) {
    int et = blockIdx.x;
    int t = threadIdx.x, lane = t & 31, wd = t >> 5;
    int v = (t < nb) ? g_bsums[et][t] : 0;
    int orig = v;
#pragma unroll
    for (int off = 1; off < 32; off <<= 1) {
        int u = __shfl_up_sync(0xffffffffu, v, off);
        if (lane >= off) v += u;
    }
    __shared__ int wtot;
    if (wd == 0 && lane == 31) wtot = v;
    __syncthreads();
    if (wd == 1) v += wtot;
    if (t < nb) g_bsums[et][t] = v - orig;
}
__global__ void k_scan3() {
    int et = blockIdx.y;
    int idx = blockIdx.x * 1024 + threadIdx.x;
    if (idx < NN) {
        int v = g_rowptr[et][idx + 1] + g_bsums[et][blockIdx.x];
        g_rowptr[et][idx + 1] = v;
        if (idx + 1 < NN) g_cursor[et][idx + 1] = v;
    }
    if (idx == 0) { g_rowptr[et][0] = 0; g_cursor[et][0] = 0; }
}
__global__ void k_scatter2(const int* __restrict__ eis, const int* __restrict__ eit) {
    int et = blockIdx.y;
    const int* ei = et ? eit : eis;
    int e = blockIdx.x * blockDim.x + threadIdx.x;
    if (e < EE) {
        int dst = ei[EE + e];
        int pos = atomicAdd(&g_cursor[et][dst], 1);
        g_colidx[et][pos] = ei[e];
    }
}

// ---------------- aggregation + fused BN stats (round-13 validated) ----------
__device__ __forceinline__ float lrelu02(float x) { return x > 0.f ? x : 0.2f * x; }

__global__ __launch_bounds__(256) void k_agg(int et, const float* __restrict__ bias, int buf) {
    __shared__ float ssum[8 * 512];
    __shared__ float ssq[8 * 512];
    int gt = blockIdx.x * blockDim.x + threadIdx.x;
    int w = gt >> 5, lane = gt & 31;
    int tid = threadIdx.x, wid = tid >> 5;

    const float4 ald = *(const float4*)(g_ald + (size_t)w * 4);
    int start = g_rowptr[et][w];
    int end = g_rowptr[et][w + 1];
    int hsel = lane >> 4;

    float4 acc1 = make_float4(0, 0, 0, 0);
    float4 acc2 = make_float4(0, 0, 0, 0);
    float se0 = 0, se1 = 0, se2 = 0, se3 = 0;

#define EDGE(SRC, X0, X1, X2, X3)                                              \
    {                                                                          \
        float ex1 = hsel ? (X1) : (X0);                                        \
        float ex2 = hsel ? (X3) : (X2);                                        \
        const float4* hp = (const float4*)(g_h + (size_t)(SRC) * 256);         \
        float4 v1 = hp[lane], v2 = hp[32 + lane];                              \
        acc1.x += ex1 * v1.x; acc1.y += ex1 * v1.y;                            \
        acc1.z += ex1 * v1.z; acc1.w += ex1 * v1.w;                            \
        acc2.x += ex2 * v2.x; acc2.y += ex2 * v2.y;                            \
        acc2.z += ex2 * v2.z; acc2.w += ex2 * v2.w;                            \
    }

    // self loop
    {
        float4 als = *(const float4*)(g_als + (size_t)w * 4);
        float x0 = __expf(lrelu02(als.x + ald.x));
        float x1 = __expf(lrelu02(als.y + ald.y));
        float x2 = __expf(lrelu02(als.z + ald.z));
        float x3 = __expf(lrelu02(als.w + ald.w));
        if (lane == 0) { se0 += x0; se1 += x1; se2 += x2; se3 += x3; }
        EDGE(w, x0, x1, x2, x3);
    }

    for (int base = start; base < end; base += 32) {
        int n = min(32, end - base);
        int mysrc = 0;
        float mx0 = 0.f, mx1 = 0.f, mx2 = 0.f, mx3 = 0.f;
        if (base + lane < end) {
            mysrc = g_colidx[et][base + lane];
            float4 als = *(const float4*)(g_als + (size_t)mysrc * 4);
            mx0 = __expf(lrelu02(als.x + ald.x));
            mx1 = __expf(lrelu02(als.y + ald.y));
            mx2 = __expf(lrelu02(als.z + ald.z));
            mx3 = __expf(lrelu02(als.w + ald.w));
            se0 += mx0; se1 += mx1; se2 += mx2; se3 += mx3;
        }
        int j = 0;
        for (; j + 4 <= n; j += 4) {
            int src0 = __shfl_sync(0xffffffffu, mysrc, j);
            int src1 = __shfl_sync(0xffffffffu, mysrc, j + 1);
            int src2 = __shfl_sync(0xffffffffu, mysrc, j + 2);
            int src3 = __shfl_sync(0xffffffffu, mysrc, j + 3);
            float e0, e1, e2, e3;
            {
                float a0 = __shfl_sync(0xffffffffu, mx0, j);
                float a1 = __shfl_sync(0xffffffffu, mx1, j);
                float a2 = __shfl_sync(0xffffffffu, mx2, j);
                float a3 = __shfl_sync(0xffffffffu, mx3, j);
                e0 = hsel ? a1 : a0;
                e1 = hsel ? a3 : a2;
                float b0 = __shfl_sync(0xffffffffu, mx0, j + 1);
                float b1 = __shfl_sync(0xffffffffu, mx1, j + 1);
                float b2 = __shfl_sync(0xffffffffu, mx2, j + 1);
                float b3 = __shfl_sync(0xffffffffu, mx3, j + 1);
                e2 = hsel ? b1 : b0;
                e3 = hsel ? b3 : b2;
            }
            float f0, f1, f2, f3;
            {
                float a0 = __shfl_sync(0xffffffffu, mx0, j + 2);
                float a1 = __shfl_sync(0xffffffffu, mx1, j + 2);
                float a2 = __shfl_sync(0xffffffffu, mx2, j + 2);
                float a3 = __shfl_sync(0xffffffffu, mx3, j + 2);
                f0 = hsel ? a1 : a0;
                f1 = hsel ? a3 : a2;
                float b0 = __shfl_sync(0xffffffffu, mx0, j + 3);
                float b1 = __shfl_sync(0xffffffffu, mx1, j + 3);
                float b2 = __shfl_sync(0xffffffffu, mx2, j + 3);
                float b3 = __shfl_sync(0xffffffffu, mx3, j + 3);
                f2 = hsel ? b1 : b0;
                f3 = hsel ? b3 : b2;
            }
            const float4* hp0 = (const float4*)(g_h + (size_t)src0 * 256);
            const float4* hp1 = (const float4*)(g_h + (size_t)src1 * 256);
            const float4* hp2 = (const float4*)(g_h + (size_t)src2 * 256);
            const float4* hp3 = (const float4*)(g_h + (size_t)src3 * 256);
            float4 vA1 = hp0[lane], vA2 = hp0[32 + lane];
            float4 vB1 = hp1[lane], vB2 = hp1[32 + lane];
            float4 vC1 = hp2[lane], vC2 = hp2[32 + lane];
            float4 vD1 = hp3[lane], vD2 = hp3[32 + lane];
            acc1.x += e0 * vA1.x + e2 * vB1.x + f0 * vC1.x + f2 * vD1.x;
            acc1.y += e0 * vA1.y + e2 * vB1.y + f0 * vC1.y + f2 * vD1.y;
            acc1.z += e0 * vA1.z + e2 * vB1.z + f0 * vC1.z + f2 * vD1.z;
            acc1.w += e0 * vA1.w + e2 * vB1.w + f0 * vC1.w + f2 * vD1.w;
            acc2.x += e1 * vA2.x + e3 * vB2.x + f1 * vC2.x + f3 * vD2.x;
            acc2.y += e1 * vA2.y + e3 * vB2.y + f1 * vC2.y + f3 * vD2.y;
            acc2.z += e1 * vA2.z + e3 * vB2.z + f1 * vC2.z + f3 * vD2.z;
            acc2.w += e1 * vA2.w + e3 * vB2.w + f1 * vC2.w + f3 * vD2.w;
        }
        for (; j < n; j++) {
            int src = __shfl_sync(0xffffffffu, mysrc, j);
            float x0 = __shfl_sync(0xffffffffu, mx0, j);
            float x1 = __shfl_sync(0xffffffffu, mx1, j);
            float x2 = __shfl_sync(0xffffffffu, mx2, j);
            float x3 = __shfl_sync(0xffffffffu, mx3, j);
            EDGE(src, x0, x1, x2, x3);
        }
    }
#undef EDGE

#pragma unroll
    for (int off = 16; off; off >>= 1) {
        se0 += __shfl_xor_sync(0xffffffffu, se0, off);
        se1 += __shfl_xor_sync(0xffffffffu, se1, off);
        se2 += __shfl_xor_sync(0xffffffffu, se2, off);
        se3 += __shfl_xor_sync(0xffffffffu, se3, off);
    }

    float inv1 = 1.0f / ((hsel ? se1 : se0) + 1e-16f);
    float inv2 = 1.0f / ((hsel ? se3 : se2) + 1e-16f);
    const float4* bp = (const float4*)bias;
    float4 b1 = bp[lane], b2 = bp[32 + lane];
    float4 o1 = make_float4(acc1.x * inv1 + b1.x, acc1.y * inv1 + b1.y,
                            acc1.z * inv1 + b1.z, acc1.w * inv1 + b1.w);
    float4 o2 = make_float4(acc2.x * inv2 + b2.x, acc2.y * inv2 + b2.y,
                            acc2.z * inv2 + b2.z, acc2.w * inv2 + b2.w);
    *(float4*)(g_out + (size_t)w * 256 + lane * 4) = o1;
    *(float4*)(g_out + (size_t)w * 256 + 128 + lane * 4) = o2;

    // ---- fused BN statistics ----
    ((float4*)ssum)[wid * 128 + lane] = o1;
    ((float4*)ssum)[wid * 128 + 32 + lane] = o2;
    float4 q1 = make_float4(o1.x * o1.x, o1.y * o1.y, o1.z * o1.z, o1.w * o1.w);
    float4 q2 = make_float4(o2.x * o2.x, o2.y * o2.y, o2.z * o2.z, o2.w * o2.w);
    ((float4*)ssq)[wid * 128 + lane] = q1;
    ((float4*)ssq)[wid * 128 + 32 + lane] = q2;
    __syncthreads();
    {
        int col = tid;
        float s = 0.f, q = 0.f;
#pragma unroll
        for (int wd = 0; wd < 8; wd++) {
            s += ssum[wd * 512 + col];
            q += ssq[wd * 512 + col];
        }
        atomicAdd(&g_bnstat[buf][col], s);
        atomicAdd(&g_bnstat[buf][256 + col], q);
    }
}

// ---------------- BN apply + ReLU + bf16 hi/lo split (layers 0-2) ------------
__global__ void k_bnsplit(int buf, const float* __restrict__ gam,
                          const float* __restrict__ bet) {
    int i = blockIdx.x * blockDim.x + threadIdx.x;
    if (i < 512) g_bnstat[buf ^ 1][i] = 0.0f;
    if (i >= NN * 64) return;
    int colb = (i & 63) * 4;
    float4 v = ((const float4*)g_out)[i];
    float invN = 1.0f / (float)NN;
    float out[4];
    float vv[4] = {v.x, v.y, v.z, v.w};
#pragma unroll
    for (int c = 0; c < 4; c++) {
        float mu = g_bnstat[buf][colb + c] * invN;
        float var = g_bnstat[buf][256 + colb + c] * invN - mu * mu;
        float sc = gam[colb + c] * rsqrtf(var + EPSBN);
        float y = (vv[c] - mu) * sc + bet[colb + c];
        out[c] = y > 0.f ? y : 0.f;
    }
    uint32_t h01, l01, h23, l23;
    split2(out[0], out[1], h01, l01);
    split2(out[2], out[3], h23, l23);
    *(uint2*)(g_a_hi + (size_t)i * 4) = make_uint2(h01, h23);
    *(uint2*)(g_a_lo + (size_t)i * 4) = make_uint2(l01, l23);
}

// ---------------- fused final BN + ReLU + linear 256 -> 32 -------------------
__global__ void k_bnlin(int buf, const float* __restrict__ gam,
                        const float* __restrict__ bet,
                        const float* __restrict__ Wl, const float* __restrict__ bl,
                        float* __restrict__ out) {
    int gt = blockIdx.x * blockDim.x + threadIdx.x;
    int w = gt >> 5, lane = gt & 31;
    if (w >= NN) return;
    float invN = 1.0f / (float)NN;
    float acc = bl[lane];
    const float* orow = g_out + (size_t)w * 256;
    for (int kb = 0; kb < 256; kb += 32) {
        int col = kb + lane;
        float v = orow[col];
        float mu = g_bnstat[buf][col] * invN;
        float var = g_bnstat[buf][256 + col] * invN - mu * mu;
        float y = gam[col] * (v - mu) * rsqrtf(var + EPSBN) + bet[col];
        float av = y > 0.f ? y : 0.f;
#pragma unroll
        for (int kk = 0; kk < 32; kk++) {
            float a = __shfl_sync(0xffffffffu, av, kk);
            acc += a * Wl[(kb + kk) * 32 + lane];
        }
    }
    out[(size_t)w * 32 + lane] = acc;
}

// ---------------- launch ------------------------------------------------------
extern "C" void kernel_launch(void* const* d_in, const int* in_sizes, int n_in,
                              void* d_out, int out_size) {
    (void)in_sizes; (void)n_in; (void)out_size;
    const float* x = (const float*)d_in[0];
    const int* eis = (const int*)d_in[1];
    const int* eit = (const int*)d_in[2];
    const float* W[4]  = {(const float*)d_in[3],  (const float*)d_in[9],
                          (const float*)d_in[15], (const float*)d_in[21]};
    const float* AS[4] = {(const float*)d_in[4],  (const float*)d_in[10],
                          (const float*)d_in[16], (const float*)d_in[22]};
    const float* AD[4] = {(const float*)d_in[5],  (const float*)d_in[11],
                          (const float*)d_in[17], (const float*)d_in[23]};
    const float* BI[4] = {(const float*)d_in[6],  (const float*)d_in[12],
                          (const float*)d_in[18], (const float*)d_in[24]};
    const float* GA[4] = {(const float*)d_in[7],  (const float*)d_in[13],
                          (const float*)d_in[19], (const float*)d_in[25]};
    const float* BE[4] = {(const float*)d_in[8],  (const float*)d_in[14],
                          (const float*)d_in[20], (const float*)d_in[26]};
    const float* Wl = (const float*)d_in[27];
    const float* bl = (const float*)d_in[28];

    static cudaStream_t s1 = nullptr;
    static cudaEvent_t evFork = nullptr, evJoin = nullptr;
    if (s1 == nullptr) {
        cudaStreamCreateWithFlags(&s1, cudaStreamNonBlocking);
        cudaEventCreateWithFlags(&evFork, cudaEventDisableTiming);
        cudaEventCreateWithFlags(&evJoin, cudaEventDisableTiming);
        cudaFuncSetAttribute(k_gemm2, cudaFuncAttributeMaxDynamicSharedMemorySize,
                             SMEM_GEMM);
    }

    const int scanBlocks = (NN + 1023) / 1024;  // 49
    const int xBlocks = (NN * 32 + 255) / 256;  // 6250
    dim3 ggemm(NTILES, 2);

    // main stream: fused prep + layer-0 GEMM
    k_prep<<<1024 + xBlocks, 256>>>(x, W[0], W[1], W[2], W[3]);
    cudaEventRecord(evFork, 0);
    k_gemm2<<<ggemm, 256, SMEM_GEMM>>>(128, 0);

    // forked stream: full CSR build for both edge types
    cudaStreamWaitEvent(s1, evFork, 0);
    k_zero_deg<<<(2 * NN + 255) / 256, 256, 0, s1>>>();
    k_hist2<<<(EE + 255) / 256, 256, 0, s1>>>(eis, eit);
    k_scan1<<<dim3(scanBlocks, 2), 1024, 0, s1>>>();
    k_scan2<<<2, 64, 0, s1>>>(scanBlocks);
    k_scan3<<<dim3(scanBlocks, 2), 1024, 0, s1>>>();
    k_scatter2<<<dim3((EE + 255) / 256, 2), 256, 0, s1>>>(eis, eit);
    cudaEventRecord(evJoin, s1);

    k_al<<<(NN * 32 + 255) / 256, 256>>>(AS[0], AD[0]);
    cudaStreamWaitEvent(0, evJoin, 0);

    int ET[4] = {0, 0, 1, 1};
    for (int l = 0; l < 4; l++) {
        if (l > 0) {
            k_gemm2<<<ggemm, 256, SMEM_GEMM>>>(256, l);
            k_al<<<(NN * 32 + 255) / 256, 256>>>(AS[l], AD[l]);
        }
        k_agg<<<(NN * 32 + 255) / 256, 256>>>(ET[l], BI[l], l & 1);
        if (l < 3) {
            k_bnsplit<<<(NN * 64 + 255) / 256, 256>>>(l & 1, GA[l], BE[l]);
        } else {
            k_bnlin<<<(NN * 32 + 255) / 256, 256>>>(l & 1, GA[l], BE[l], Wl, bl,
                                                    (float*)d_out);
        }
    }
}

// round 16
// speedup vs baseline: 1.0497x; 1.0274x over previous
#include <cuda_runtime.h>
#include <cuda_bf16.h>
#include <cuda_fp16.h>
#include <mma.h>
#include <cstdint>
#include <cstddef>

using namespace nvcuda;

#define NN 50000
#define NPAD 50048  // 391 * 128
#define EE 800000
#define EPSBN 1e-5f
#define NTILES 391

// ---------------- scratch (static device globals) ---------------------------
__device__ __align__(256) float g_h[(size_t)NPAD * 256];
__device__ __align__(256) __half g_hx[(size_t)NPAD * 256];  // fp16 h for gather
__device__ __align__(256) float g_out[(size_t)NN * 256];
__device__ __align__(256) float g_als[NN * 4];
__device__ __align__(256) float g_ald[NN * 4];
__device__ __align__(256) int   g_rowptr[2][NN + 1];
__device__ __align__(256) int   g_colidx[2][EE];
__device__ __align__(256) int   g_deg[2][NN];
__device__ __align__(256) int   g_cursor[2][NN];
__device__ __align__(256) int   g_bsums[2][64];
__device__ __align__(256) float g_bnstat[2][512];
__device__ __align__(256) __nv_bfloat16 g_wt_hi[4 * 256 * 256];  // [layer][n][k]
__device__ __align__(256) __nv_bfloat16 g_wt_lo[4 * 256 * 256];
__device__ __align__(256) __nv_bfloat16 g_a_hi[(size_t)NPAD * 256];
__device__ __align__(256) __nv_bfloat16 g_a_lo[(size_t)NPAD * 256];

__device__ __forceinline__ void split2(float a, float b, uint32_t& hi, uint32_t& lo) {
    __nv_bfloat162 h = __floats2bfloat162_rn(a, b);
    hi = *reinterpret_cast<uint32_t*>(&h);
    float ra = a - __bfloat162float(h.x);
    float rb = b - __bfloat162float(h.y);
    __nv_bfloat162 l = __floats2bfloat162_rn(ra, rb);
    lo = *reinterpret_cast<uint32_t*>(&l);
}

__device__ __forceinline__ uint32_t smem_u32(const void* p) {
    uint32_t a;
    asm("{ .reg .u64 t; cvta.to.shared.u64 t, %1; cvt.u32.u64 %0, t; }" : "=r"(a) : "l"(p));
    return a;
}
__device__ __forceinline__ void cp16(uint32_t s, const void* g) {
    asm volatile("cp.async.cg.shared.global [%0], [%1], 16;" :: "r"(s), "l"(g));
}
#define CP_COMMIT asm volatile("cp.async.commit_group;")

// ---------------- fused prep: W split + x split + bn zero --------------------
__global__ void k_prep(const float* __restrict__ x,
                       const float* __restrict__ W1, const float* __restrict__ W2,
                       const float* __restrict__ W3, const float* __restrict__ W4) {
    int b = blockIdx.x;
    int tid = threadIdx.x;
    if (b < 2) {
        g_bnstat[b][tid] = 0.0f;
        g_bnstat[b][tid + 256] = 0.0f;
    }
    if (b < 1024) {
        int layer = b >> 8;
        const float* W = layer == 0 ? W1 : layer == 1 ? W2 : layer == 2 ? W3 : W4;
        int K = layer == 0 ? 128 : 256;
        int i = (b & 255) * 256 + tid;  // i = n*256 + k
        int n = i >> 8, k = i & 255;
        float v = (k < K) ? W[k * 256 + n] : 0.0f;
        __nv_bfloat16 h = __float2bfloat16_rn(v);
        float lo = v - __bfloat162float(h);
        g_wt_hi[layer * 65536 + i] = h;
        g_wt_lo[layer * 65536 + i] = __float2bfloat16_rn(lo);
    } else {
        int i = (b - 1024) * 256 + tid;  // over NN*32 float4s
        if (i >= NN * 32) return;
        float4 v = ((const float4*)x)[i];
        uint32_t h01, l01, h23, l23;
        split2(v.x, v.y, h01, l01);
        split2(v.z, v.w, h23, l23);
        *(uint2*)(g_a_hi + (size_t)i * 4) = make_uint2(h01, h23);
        *(uint2*)(g_a_lo + (size_t)i * 4) = make_uint2(l01, l23);
    }
}

// ---------------- WMMA bf16 split GEMM, 2 CTAs/SM (round-11 proven) ----------
typedef wmma::fragment<wmma::matrix_a, 16, 16, 16, __nv_bfloat16, wmma::row_major> FragA;
typedef wmma::fragment<wmma::matrix_b, 16, 16, 16, __nv_bfloat16, wmma::col_major> FragB;
typedef wmma::fragment<wmma::accumulator, 16, 16, 16, float> FragC;

#define SSTR 40
#define PSTG 5120
#define SMEM_GEMM 81920

__global__ __launch_bounds__(256, 2) void k_gemm2(int K, int layer) {
    extern __shared__ __nv_bfloat16 sm[];
    const __nv_bfloat16* gAh = g_a_hi;
    const __nv_bfloat16* gAl = g_a_lo;
    const __nv_bfloat16* gBh = g_wt_hi + layer * 65536;
    const __nv_bfloat16* gBl = g_wt_lo + layer * 65536;
    int tid = threadIdx.x, wid = tid >> 5;
    int tbM = blockIdx.x * 128, tbN = blockIdx.y * 128;
    int wm = wid & 1, wn = wid >> 1;
    uint32_t sbase = smem_u32(sm);

    FragC acc[4][2];
#pragma unroll
    for (int i = 0; i < 4; i++)
#pragma unroll
        for (int j = 0; j < 2; j++) wmma::fill_fragment(acc[i][j], 0.0f);

    int nch = K >> 5;

#define PREFETCH(stage, k0)                                                        \
    {                                                                              \
        _Pragma("unroll")                                                          \
        for (int r = 0; r < 2; r++) {                                              \
            int q = r * 256 + tid;                                                 \
            int row = q >> 2;                                                      \
            int cq = (q & 3) * 8;                                                  \
            size_t ga = (size_t)(tbM + row) * K + (k0) + cq;                       \
            size_t gb = (size_t)(tbN + row) * 256 + (k0) + cq;                     \
            uint32_t so = (uint32_t)(((stage) * 2) * PSTG + row * SSTR + cq) * 2;  \
            cp16(sbase + so, gAh + ga);                                            \
            cp16(sbase + so + PSTG * 2, gAl + ga);                                 \
            cp16(sbase + so + 4 * PSTG * 2, gBh + gb);                             \
            cp16(sbase + so + 5 * PSTG * 2, gBl + gb);                             \
        }                                                                          \
    }

    PREFETCH(0, 0);
    CP_COMMIT;
    for (int c = 0; c < nch; c++) {
        if (c + 1 < nch) {
            PREFETCH((c + 1) & 1, (c + 1) * 32);
            CP_COMMIT;
            asm volatile("cp.async.wait_group 1;");
        } else {
            asm volatile("cp.async.wait_group 0;");
        }
        __syncthreads();
        int st = c & 1;
        const __nv_bfloat16* pAh = sm + (st * 2 + 0) * PSTG;
        const __nv_bfloat16* pAl = sm + (st * 2 + 1) * PSTG;
        const __nv_bfloat16* pBh = sm + 4 * PSTG + (st * 2 + 0) * PSTG;
        const __nv_bfloat16* pBl = sm + 4 * PSTG + (st * 2 + 1) * PSTG;
#pragma unroll
        for (int ks = 0; ks < 32; ks += 16) {
            FragB bhi[2], blo[2];
#pragma unroll
            for (int j = 0; j < 2; j++) {
                wmma::load_matrix_sync(bhi[j], &pBh[(wn * 32 + j * 16) * SSTR + ks], SSTR);
                wmma::load_matrix_sync(blo[j], &pBl[(wn * 32 + j * 16) * SSTR + ks], SSTR);
            }
#pragma unroll
            for (int i = 0; i < 4; i++) {
                FragA ah, al;
                wmma::load_matrix_sync(ah, &pAh[(wm * 64 + i * 16) * SSTR + ks], SSTR);
                wmma::load_matrix_sync(al, &pAl[(wm * 64 + i * 16) * SSTR + ks], SSTR);
#pragma unroll
                for (int j = 0; j < 2; j++) {
                    wmma::mma_sync(acc[i][j], ah, bhi[j], acc[i][j]);
                    wmma::mma_sync(acc[i][j], ah, blo[j], acc[i][j]);
                    wmma::mma_sync(acc[i][j], al, bhi[j], acc[i][j]);
                }
            }
        }
        __syncthreads();
    }

#pragma unroll
    for (int i = 0; i < 4; i++)
#pragma unroll
        for (int j = 0; j < 2; j++)
            wmma::store_matrix_sync(
                g_h + (size_t)(tbM + wm * 64 + i * 16) * 256 + tbN + wn * 32 + j * 16,
                acc[i][j], 256, wmma::mem_row_major);
}

// ---------------- attention logits + fp16 h conversion -----------------------
__global__ void k_al(const float* __restrict__ as_, const float* __restrict__ ad_) {
    int gt = blockIdx.x * blockDim.x + threadIdx.x;
    int w = gt >> 5, lane = gt & 31;
    if (w >= NN) return;
    const float4* hp = (const float4*)(g_h + (size_t)w * 256);
    float4 h1 = hp[lane * 2], h2 = hp[lane * 2 + 1];
    // fp16 copy for the aggregation gather (free: data already in registers)
    {
        __half2 p0 = __floats2half2_rn(h1.x, h1.y);
        __half2 p1 = __floats2half2_rn(h1.z, h1.w);
        __half2 p2 = __floats2half2_rn(h2.x, h2.y);
        __half2 p3 = __floats2half2_rn(h2.z, h2.w);
        uint4 pk = make_uint4(*(uint32_t*)&p0, *(uint32_t*)&p1,
                              *(uint32_t*)&p2, *(uint32_t*)&p3);
        *(uint4*)(g_hx + (size_t)w * 256 + lane * 8) = pk;
    }
    const float4* sp = (const float4*)as_;
    const float4* dp = (const float4*)ad_;
    float4 s1 = sp[lane * 2], s2 = sp[lane * 2 + 1];
    float4 d1 = dp[lane * 2], d2 = dp[lane * 2 + 1];
    float vs = h1.x * s1.x + h1.y * s1.y + h1.z * s1.z + h1.w * s1.w +
               h2.x * s2.x + h2.y * s2.y + h2.z * s2.z + h2.w * s2.w;
    float vd = h1.x * d1.x + h1.y * d1.y + h1.z * d1.z + h1.w * d1.w +
               h2.x * d2.x + h2.y * d2.y + h2.z * d2.z + h2.w * d2.w;
    vs += __shfl_down_sync(0xffffffffu, vs, 4, 8);
    vs += __shfl_down_sync(0xffffffffu, vs, 2, 8);
    vs += __shfl_down_sync(0xffffffffu, vs, 1, 8);
    vd += __shfl_down_sync(0xffffffffu, vd, 4, 8);
    vd += __shfl_down_sync(0xffffffffu, vd, 2, 8);
    vd += __shfl_down_sync(0xffffffffu, vd, 1, 8);
    if ((lane & 7) == 0) {
        g_als[w * 4 + (lane >> 3)] = vs;
        g_ald[w * 4 + (lane >> 3)] = vd;
    }
}

// ---------------- small utility kernels --------------------------------------
__global__ void k_zero_deg() {
    int i = blockIdx.x * blockDim.x + threadIdx.x;
    if (i < 2 * NN) ((int*)g_deg)[i] = 0;
}

// ---------------- CSR build (batched over both edge types) -------------------
__global__ void k_hist2(const int* __restrict__ eis, const int* __restrict__ eit) {
    int e = blockIdx.x * blockDim.x + threadIdx.x;
    if (e < EE) {
        atomicAdd(&g_deg[0][eis[EE + e]], 1);
        atomicAdd(&g_deg[1][eit[EE + e]], 1);
    }
}
__global__ void k_scan1() {
    int et = blockIdx.y;
    __shared__ int sm[1024];
    int t = threadIdx.x;
    int idx = blockIdx.x * 1024 + t;
    int v = (idx < NN) ? g_deg[et][idx] : 0;
    sm[t] = v;
    __syncthreads();
    for (int off = 1; off < 1024; off <<= 1) {
        int u = (t >= off) ? sm[t - off] : 0;
        __syncthreads();
        sm[t] += u;
        __syncthreads();
    }
    if (idx < NN) g_rowptr[et][idx + 1] = sm[t];
    if (t == 1023) g_bsums[et][blockIdx.x] = sm[1023];
}
__global__ void k_scan2(int nb) {
    int et = blockIdx.x;
    int t = threadIdx.x, lane = t & 31, wd = t >> 5;
    int v = (t < nb) ? g_bsums[et][t] : 0;
    int orig = v;
#pragma unroll
    for (int off = 1; off < 32; off <<= 1) {
        int u = __shfl_up_sync(0xffffffffu, v, off);
        if (lane >= off) v += u;
    }
    __shared__ int wtot;
    if (wd == 0 && lane == 31) wtot = v;
    __syncthreads();
    if (wd == 1) v += wtot;
    if (t < nb) g_bsums[et][t] = v - orig;
}
__global__ void k_scan3() {
    int et = blockIdx.y;
    int idx = blockIdx.x * 1024 + threadIdx.x;
    if (idx < NN) {
        int v = g_rowptr[et][idx + 1] + g_bsums[et][blockIdx.x];
        g_rowptr[et][idx + 1] = v;
        if (idx + 1 < NN) g_cursor[et][idx + 1] = v;
    }
    if (idx == 0) { g_rowptr[et][0] = 0; g_cursor[et][0] = 0; }
}
__global__ void k_scatter2(const int* __restrict__ eis, const int* __restrict__ eit) {
    int et = blockIdx.y;
    const int* ei = et ? eit : eis;
    int e = blockIdx.x * blockDim.x + threadIdx.x;
    if (e < EE) {
        int dst = ei[EE + e];
        int pos = atomicAdd(&g_cursor[et][dst], 1);
        g_colidx[et][pos] = ei[e];
    }
}

// ---------------- aggregation (fp16 gather) + fused BN stats -----------------
__device__ __forceinline__ float lrelu02(float x) { return x > 0.f ? x : 0.2f * x; }

__global__ __launch_bounds__(256) void k_agg(int et, const float* __restrict__ bias, int buf) {
    __shared__ float ssum[8 * 512];
    __shared__ float ssq[8 * 512];
    int gt = blockIdx.x * blockDim.x + threadIdx.x;
    int w = gt >> 5, lane = gt & 31;
    int tid = threadIdx.x, wid = tid >> 5;

    const float4 ald = *(const float4*)(g_ald + (size_t)w * 4);
    int start = g_rowptr[et][w];
    int end = g_rowptr[et][w + 1];

    float acc[8];
#pragma unroll
    for (int i = 0; i < 8; i++) acc[i] = 0.f;
    float se0 = 0, se1 = 0, se2 = 0, se3 = 0;

#define GATHER(SRC, X0, X1, X2, X3)                                            \
    {                                                                          \
        float ex = (lane & 16) ? ((lane & 8) ? (X3) : (X2))                    \
                               : ((lane & 8) ? (X1) : (X0));                   \
        uint4 hv = *(const uint4*)(g_hx + (size_t)(SRC) * 256 + lane * 8);     \
        __half2* hq = (__half2*)&hv;                                           \
        _Pragma("unroll")                                                      \
        for (int q = 0; q < 4; q++) {                                          \
            float2 f = __half22float2(hq[q]);                                  \
            acc[2 * q] += ex * f.x;                                            \
            acc[2 * q + 1] += ex * f.y;                                        \
        }                                                                      \
    }

    // self loop
    {
        float4 als = *(const float4*)(g_als + (size_t)w * 4);
        float x0 = __expf(lrelu02(als.x + ald.x));
        float x1 = __expf(lrelu02(als.y + ald.y));
        float x2 = __expf(lrelu02(als.z + ald.z));
        float x3 = __expf(lrelu02(als.w + ald.w));
        if (lane == 0) { se0 += x0; se1 += x1; se2 += x2; se3 += x3; }
        GATHER(w, x0, x1, x2, x3);
    }

    for (int base = start; base < end; base += 32) {
        int n = min(32, end - base);
        int mysrc = 0;
        float mx0 = 0.f, mx1 = 0.f, mx2 = 0.f, mx3 = 0.f;
        if (base + lane < end) {
            mysrc = g_colidx[et][base + lane];
            float4 als = *(const float4*)(g_als + (size_t)mysrc * 4);
            mx0 = __expf(lrelu02(als.x + ald.x));
            mx1 = __expf(lrelu02(als.y + ald.y));
            mx2 = __expf(lrelu02(als.z + ald.z));
            mx3 = __expf(lrelu02(als.w + ald.w));
            se0 += mx0; se1 += mx1; se2 += mx2; se3 += mx3;
        }
        int j = 0;
        for (; j + 2 <= n; j += 2) {
            int srcA = __shfl_sync(0xffffffffu, mysrc, j);
            int srcB = __shfl_sync(0xffffffffu, mysrc, j + 1);
            float a0 = __shfl_sync(0xffffffffu, mx0, j);
            float a1 = __shfl_sync(0xffffffffu, mx1, j);
            float a2 = __shfl_sync(0xffffffffu, mx2, j);
            float a3 = __shfl_sync(0xffffffffu, mx3, j);
            float b0 = __shfl_sync(0xffffffffu, mx0, j + 1);
            float b1 = __shfl_sync(0xffffffffu, mx1, j + 1);
            float b2 = __shfl_sync(0xffffffffu, mx2, j + 1);
            float b3 = __shfl_sync(0xffffffffu, mx3, j + 1);
            float exA = (lane & 16) ? ((lane & 8) ? a3 : a2) : ((lane & 8) ? a1 : a0);
            float exB = (lane & 16) ? ((lane & 8) ? b3 : b2) : ((lane & 8) ? b1 : b0);
            uint4 hvA = *(const uint4*)(g_hx + (size_t)srcA * 256 + lane * 8);
            uint4 hvB = *(const uint4*)(g_hx + (size_t)srcB * 256 + lane * 8);
            __half2* hqA = (__half2*)&hvA;
            __half2* hqB = (__half2*)&hvB;
#pragma unroll
            for (int q = 0; q < 4; q++) {
                float2 fA = __half22float2(hqA[q]);
                float2 fB = __half22float2(hqB[q]);
                acc[2 * q] += exA * fA.x + exB * fB.x;
                acc[2 * q + 1] += exA * fA.y + exB * fB.y;
            }
        }
        if (j < n) {
            int src = __shfl_sync(0xffffffffu, mysrc, j);
            float x0 = __shfl_sync(0xffffffffu, mx0, j);
            float x1 = __shfl_sync(0xffffffffu, mx1, j);
            float x2 = __shfl_sync(0xffffffffu, mx2, j);
            float x3 = __shfl_sync(0xffffffffu, mx3, j);
            GATHER(src, x0, x1, x2, x3);
        }
    }
#undef GATHER

#pragma unroll
    for (int off = 16; off; off >>= 1) {
        se0 += __shfl_xor_sync(0xffffffffu, se0, off);
        se1 += __shfl_xor_sync(0xffffffffu, se1, off);
        se2 += __shfl_xor_sync(0xffffffffu, se2, off);
        se3 += __shfl_xor_sync(0xffffffffu, se3, off);
    }

    float se = (lane & 16) ? ((lane & 8) ? se3 : se2) : ((lane & 8) ? se1 : se0);
    float inv = 1.0f / (se + 1e-16f);
    float4 b1 = *(const float4*)(bias + lane * 8);
    float4 b2 = *(const float4*)(bias + lane * 8 + 4);
    float4 o1 = make_float4(acc[0] * inv + b1.x, acc[1] * inv + b1.y,
                            acc[2] * inv + b1.z, acc[3] * inv + b1.w);
    float4 o2 = make_float4(acc[4] * inv + b2.x, acc[5] * inv + b2.y,
                            acc[6] * inv + b2.z, acc[7] * inv + b2.w);
    *(float4*)(g_out + (size_t)w * 256 + lane * 8) = o1;
    *(float4*)(g_out + (size_t)w * 256 + lane * 8 + 4) = o2;

    // ---- fused BN statistics (cols lane*8 .. lane*8+7) ----
    ((float4*)ssum)[wid * 128 + lane * 2] = o1;
    ((float4*)ssum)[wid * 128 + lane * 2 + 1] = o2;
    float4 q1 = make_float4(o1.x * o1.x, o1.y * o1.y, o1.z * o1.z, o1.w * o1.w);
    float4 q2 = make_float4(o2.x * o2.x, o2.y * o2.y, o2.z * o2.z, o2.w * o2.w);
    ((float4*)ssq)[wid * 128 + lane * 2] = q1;
    ((float4*)ssq)[wid * 128 + lane * 2 + 1] = q2;
    __syncthreads();
    {
        int col = tid;
        float s = 0.f, q = 0.f;
#pragma unroll
        for (int wd = 0; wd < 8; wd++) {
            s += ssum[wd * 512 + col];
            q += ssq[wd * 512 + col];
        }
        atomicAdd(&g_bnstat[buf][col], s);
        atomicAdd(&g_bnstat[buf][256 + col], q);
    }
}

// ---------------- BN apply + ReLU + bf16 hi/lo split (layers 0-2) ------------
__global__ void k_bnsplit(int buf, const float* __restrict__ gam,
                          const float* __restrict__ bet) {
    int i = blockIdx.x * blockDim.x + threadIdx.x;
    if (i < 512) g_bnstat[buf ^ 1][i] = 0.0f;
    if (i >= NN * 64) return;
    int colb = (i & 63) * 4;
    float4 v = ((const float4*)g_out)[i];
    float invN = 1.0f / (float)NN;
    float out[4];
    float vv[4] = {v.x, v.y, v.z, v.w};
#pragma unroll
    for (int c = 0; c < 4; c++) {
        float mu = g_bnstat[buf][colb + c] * invN;
        float var = g_bnstat[buf][256 + colb + c] * invN - mu * mu;
        float sc = gam[colb + c] * rsqrtf(var + EPSBN);
        float y = (vv[c] - mu) * sc + bet[colb + c];
        out[c] = y > 0.f ? y : 0.f;
    }
    uint32_t h01, l01, h23, l23;
    split2(out[0], out[1], h01, l01);
    split2(out[2], out[3], h23, l23);
    *(uint2*)(g_a_hi + (size_t)i * 4) = make_uint2(h01, h23);
    *(uint2*)(g_a_lo + (size_t)i * 4) = make_uint2(l01, l23);
}

// ---------------- fused final BN + ReLU + linear 256 -> 32 -------------------
__global__ void k_bnlin(int buf, const float* __restrict__ gam,
                        const float* __restrict__ bet,
                        const float* __restrict__ Wl, const float* __restrict__ bl,
                        float* __restrict__ out) {
    int gt = blockIdx.x * blockDim.x + threadIdx.x;
    int w = gt >> 5, lane = gt & 31;
    if (w >= NN) return;
    float invN = 1.0f / (float)NN;
    float acc = bl[lane];
    const float* orow = g_out + (size_t)w * 256;
    for (int kb = 0; kb < 256; kb += 32) {
        int col = kb + lane;
        float v = orow[col];
        float mu = g_bnstat[buf][col] * invN;
        float var = g_bnstat[buf][256 + col] * invN - mu * mu;
        float y = gam[col] * (v - mu) * rsqrtf(var + EPSBN) + bet[col];
        float av = y > 0.f ? y : 0.f;
#pragma unroll
        for (int kk = 0; kk < 32; kk++) {
            float a = __shfl_sync(0xffffffffu, av, kk);
            acc += a * Wl[(kb + kk) * 32 + lane];
        }
    }
    out[(size_t)w * 32 + lane] = acc;
}

// ---------------- launch ------------------------------------------------------
extern "C" void kernel_launch(void* const* d_in, const int* in_sizes, int n_in,
                              void* d_out, int out_size) {
    (void)in_sizes; (void)n_in; (void)out_size;
    const float* x = (const float*)d_in[0];
    const int* eis = (const int*)d_in[1];
    const int* eit = (const int*)d_in[2];
    const float* W[4]  = {(const float*)d_in[3],  (const float*)d_in[9],
                          (const float*)d_in[15], (const float*)d_in[21]};
    const float* AS[4] = {(const float*)d_in[4],  (const float*)d_in[10],
                          (const float*)d_in[16], (const float*)d_in[22]};
    const float* AD[4] = {(const float*)d_in[5],  (const float*)d_in[11],
                          (const float*)d_in[17], (const float*)d_in[23]};
    const float* BI[4] = {(const float*)d_in[6],  (const float*)d_in[12],
                          (const float*)d_in[18], (const float*)d_in[24]};
    const float* GA[4] = {(const float*)d_in[7],  (const float*)d_in[13],
                          (const float*)d_in[19], (const float*)d_in[25]};
    const float* BE[4] = {(const float*)d_in[8],  (const float*)d_in[14],
                          (const float*)d_in[20], (const float*)d_in[26]};
    const float* Wl = (const float*)d_in[27];
    const float* bl = (const float*)d_in[28];

    static cudaStream_t s1 = nullptr;
    static cudaEvent_t evFork = nullptr, evJoin = nullptr;
    if (s1 == nullptr) {
        cudaStreamCreateWithFlags(&s1, cudaStreamNonBlocking);
        cudaEventCreateWithFlags(&evFork, cudaEventDisableTiming);
        cudaEventCreateWithFlags(&evJoin, cudaEventDisableTiming);
        cudaFuncSetAttribute(k_gemm2, cudaFuncAttributeMaxDynamicSharedMemorySize,
                             SMEM_GEMM);
    }

    const int scanBlocks = (NN + 1023) / 1024;  // 49
    const int xBlocks = (NN * 32 + 255) / 256;  // 6250
    dim3 ggemm(NTILES, 2);

    // main stream: fused prep + layer-0 GEMM
    k_prep<<<1024 + xBlocks, 256>>>(x, W[0], W[1], W[2], W[3]);
    cudaEventRecord(evFork, 0);
    k_gemm2<<<ggemm, 256, SMEM_GEMM>>>(128, 0);

    // forked stream: full CSR build for both edge types
    cudaStreamWaitEvent(s1, evFork, 0);
    k_zero_deg<<<(2 * NN + 255) / 256, 256, 0, s1>>>();
    k_hist2<<<(EE + 255) / 256, 256, 0, s1>>>(eis, eit);
    k_scan1<<<dim3(scanBlocks, 2), 1024, 0, s1>>>();
    k_scan2<<<2, 64, 0, s1>>>(scanBlocks);
    k_scan3<<<dim3(scanBlocks, 2), 1024, 0, s1>>>();
    k_scatter2<<<dim3((EE + 255) / 256, 2), 256, 0, s1>>>(eis, eit);
    cudaEventRecord(evJoin, s1);

    k_al<<<(NN * 32 + 255) / 256, 256>>>(AS[0], AD[0]);
    cudaStreamWaitEvent(0, evJoin, 0);

    int ET[4] = {0, 0, 1, 1};
    for (int l = 0; l < 4; l++) {
        if (l > 0) {
            k_gemm2<<<ggemm, 256, SMEM_GEMM>>>(256, l);
            k_al<<<(NN * 32 + 255) / 256, 256>>>(AS[l], AD[l]);
        }
        k_agg<<<(NN * 32 + 255) / 256, 256>>>(ET[l], BI[l], l & 1);
        if (l < 3) {
            k_bnsplit<<<(NN * 64 + 255) / 256, 256>>>(l & 1, GA[l], BE[l]);
        } else {
            k_bnlin<<<(NN * 32 + 255) / 256, 256>>>(l & 1, GA[l], BE[l], Wl, bl,
                                                    (float*)d_out);
        }
    }
}